// round 13
// baseline (speedup 1.0000x reference)
#include <cuda_runtime.h>
#include <cuda_bf16.h>
#include <cstdint>

// NaiveVisCache R12: TMA-staged streams + u16-packed L2-resident ratio table.
//  Phase 1 (unchanged, R11 best): pack (n | d<<8) u16 -> 25MB table,
//           evict_last, 4 entries/thread. ~16us (DRAM floor).
//  Phase 2: gather kernel is L1tex-WAVEFRONT bound, and ~45% of the
//           wavefronts were the coalesced float4 streams (6x16 wf + store).
//           Move origins/dirs into SMEM via cp.async.bulk (TMA path, no
//           L1tex wavefronts); threads read from SMEM (LDS, cheap), then do
//           the 4 irreducible divergent gathers per thread. 1024 rays/block,
//           28KB smem -> 8 blocks/SM, full occupancy.
// Numerics bit-exact (rel_err 0.0 since R4): face via rcp.rn+mul, output via
// fdiv_rn on exact small-int n,d from the packed u16.

#define VGRID 128
#define TABLE_N (VGRID * VGRID * VGRID * 6)   // 12,582,912 entries
#define RAYS_PER_BLOCK 1024
#define TILE_FLOATS (RAYS_PER_BLOCK * 3)      // 3072 floats = 12288 bytes
#define TILE_BYTES  (TILE_FLOATS * 4)

__device__ unsigned short g_pack[TABLE_N];    // 25.2MB static scratch

__device__ __forceinline__ unsigned long long evict_last_policy() {
    unsigned long long pol;
    asm("createpolicy.fractional.L2::evict_last.b64 %0, 1.0;" : "=l"(pol));
    return pol;
}

// ---------------- Phase 1: pack tables (4 entries/thread) ----------------
__global__ void __launch_bounds__(256)
pack_kernel(const int4* __restrict__ numer4,
            const int4* __restrict__ denom4,
            int nvec) {
    int t = blockIdx.x * blockDim.x + threadIdx.x;
    if (t >= nvec) return;
    unsigned long long pol = evict_last_policy();

    int4 n = __ldcs(numer4 + t);   // touch-once streams
    int4 d = __ldcs(denom4 + t);
    unsigned int lo = (unsigned int)(n.x | (d.x << 8)) |
                      ((unsigned int)(n.y | (d.y << 8)) << 16);
    unsigned int hi = (unsigned int)(n.z | (d.z << 8)) |
                      ((unsigned int)(n.w | (d.w << 8)) << 16);
    unsigned long long v = (unsigned long long)lo | ((unsigned long long)hi << 32);
    asm volatile("st.global.L2::cache_hint.b64 [%0], %1, %2;"
                 :: "l"((unsigned long long*)(g_pack + 4 * (size_t)t)),
                    "l"(v), "l"(pol));
}

// ---------------- index math (bit-exact vs reference) ----------------
__device__ __forceinline__ int coord_clip(float o) {
    float t = (o * 0.5f + 0.5f) * (float)(VGRID - 1);
    t = fminf(fmaxf(t, 0.0f), (float)(VGRID - 1));
    return (int)t;
}

__device__ __forceinline__ int ray_index(float o0, float o1, float o2,
                                         float d0, float d1, float d2) {
    float inf = fmaxf(fabsf(d0), fmaxf(fabsf(d1), fabsf(d2)));
    // Reference: sqdirs = viewdirs * RN(1/inf_norm) (verified bit-exact, R4).
    float rinf = __frcp_rn(inf);
    float sa = d0 * rinf;
    float sb = d1 * rinf;
    float sc = d2 * rinf;
    int f = 0;
    if (sa >=  1.0f) f = 0;
    if (sa <= -1.0f) f = 1;
    if (sb >=  1.0f) f = 2;
    if (sb <= -1.0f) f = 3;
    if (sc >=  1.0f) f = 4;
    if (sc <= -1.0f) f = 5;
    int i = coord_clip(o0);
    int j = coord_clip(o1);
    int k = coord_clip(o2);
    return (((i * VGRID + j) * VGRID + k) * 6) + f;
}

__device__ __forceinline__ unsigned int gather_pack(int idx,
                                                    unsigned long long pol) {
    unsigned int v;
    asm volatile("ld.global.nc.L2::cache_hint.u16 %0, [%1], %2;"
                 : "=r"(v) : "l"(g_pack + idx), "l"(pol));
    return v;
}

__device__ __forceinline__ float decode_div(unsigned int p) {
    float n = (float)(int)(p & 0xFFu);
    float d = (float)(int)(p >> 8);
    return __fdiv_rn(n, d);   // same instruction/values as reference path
}

// ---------------- Phase 2: TMA-staged gather, 1024 rays/block -------------
__global__ void __launch_bounds__(256, 8)
vis_cache_kernel(const float* __restrict__ origins,
                 const float* __restrict__ dirs,
                 float4*      __restrict__ out) {
    __shared__ alignas(16) float s_o[TILE_FLOATS];
    __shared__ alignas(16) float s_v[TILE_FLOATS];
    __shared__ alignas(8) unsigned long long s_mbar;

    int tid = threadIdx.x;
    size_t base = (size_t)blockIdx.x * TILE_FLOATS;

    uint32_t mbar_a, dst_o, dst_v;
    asm("{ .reg .u64 t; cvta.to.shared.u64 t, %1; cvt.u32.u64 %0, t; }"
        : "=r"(mbar_a) : "l"(&s_mbar));
    asm("{ .reg .u64 t; cvta.to.shared.u64 t, %1; cvt.u32.u64 %0, t; }"
        : "=r"(dst_o) : "l"(s_o));
    asm("{ .reg .u64 t; cvta.to.shared.u64 t, %1; cvt.u32.u64 %0, t; }"
        : "=r"(dst_v) : "l"(s_v));

    if (tid == 0) {
        asm volatile("mbarrier.init.shared.b64 [%0], %1;"
                     :: "r"(mbar_a), "r"(1u) : "memory");
    }
    __syncthreads();
    if (tid == 0) {
        asm volatile("mbarrier.arrive.expect_tx.shared.b64 _, [%0], %1;"
                     :: "r"(mbar_a), "r"(2u * TILE_BYTES) : "memory");
        asm volatile("cp.async.bulk.shared::cluster.global"
                     ".mbarrier::complete_tx::bytes [%0], [%1], %2, [%3];"
                     :: "r"(dst_o), "l"(origins + base), "r"(TILE_BYTES),
                        "r"(mbar_a) : "memory");
        asm volatile("cp.async.bulk.shared::cluster.global"
                     ".mbarrier::complete_tx::bytes [%0], [%1], %2, [%3];"
                     :: "r"(dst_v), "l"(dirs + base), "r"(TILE_BYTES),
                        "r"(mbar_a) : "memory");
    }
    // Wait for both TMA loads (parity 0; barrier used once per block).
    {
        uint32_t done;
        asm volatile(
            "{\n\t.reg .pred p;\n\t"
            "mbarrier.try_wait.parity.shared.b64 p, [%1], %2;\n\t"
            "selp.b32 %0, 1, 0, p;\n\t}"
            : "=r"(done) : "r"(mbar_a), "r"(0u) : "memory");
        while (!done) {
            asm volatile(
                "{\n\t.reg .pred p;\n\t"
                "mbarrier.try_wait.parity.shared.b64 p, [%1], %2;\n\t"
                "selp.b32 %0, 1, 0, p;\n\t}"
                : "=r"(done) : "r"(mbar_a), "r"(0u) : "memory");
        }
    }

    unsigned long long pol = evict_last_policy();

    // 4 rays/thread from SMEM: floats [12*tid .. 12*tid+11], 16B-aligned.
    const float4* so4 = (const float4*)(s_o + 12 * tid);
    const float4* sv4 = (const float4*)(s_v + 12 * tid);
    float4 oa = so4[0], ob = so4[1], oc = so4[2];
    float4 va = sv4[0], vb = sv4[1], vc = sv4[2];

    int idx0 = ray_index(oa.x, oa.y, oa.z, va.x, va.y, va.z);
    int idx1 = ray_index(oa.w, ob.x, ob.y, va.w, vb.x, vb.y);
    int idx2 = ray_index(ob.z, ob.w, oc.x, vb.z, vb.w, vc.x);
    int idx3 = ray_index(oc.y, oc.z, oc.w, vc.y, vc.z, vc.w);

    // Batched divergent gathers (the irreducible wavefront cost).
    unsigned int p0 = gather_pack(idx0, pol);
    unsigned int p1 = gather_pack(idx1, pol);
    unsigned int p2 = gather_pack(idx2, pol);
    unsigned int p3 = gather_pack(idx3, pol);

    float4 r;
    r.x = decode_div(p0);
    r.y = decode_div(p1);
    r.z = decode_div(p2);
    r.w = decode_div(p3);
    __stcs(out + (size_t)blockIdx.x * 256 + tid, r);
}

__global__ void __launch_bounds__(256)
vis_cache_tail(const float* __restrict__ origins,
               const float* __restrict__ dirs,
               float*       __restrict__ out,
               int start, int nrays) {
    int r = start + blockIdx.x * blockDim.x + threadIdx.x;
    if (r >= nrays) return;
    int idx = ray_index(origins[3 * r], origins[3 * r + 1], origins[3 * r + 2],
                        dirs[3 * r],    dirs[3 * r + 1],    dirs[3 * r + 2]);
    unsigned int p = g_pack[idx];
    out[r] = __fdiv_rn((float)(int)(p & 0xFFu), (float)(int)(p >> 8));
}

extern "C" void kernel_launch(void* const* d_in, const int* in_sizes, int n_in,
                              void* d_out, int out_size) {
    const float* origins = (const float*)d_in[0];  // [B,3] f32
    const float* dirs    = (const float*)d_in[1];  // [B,3] f32
    const int*   numer   = (const int*)d_in[2];    // [128,128,128,6] i32
    const int*   denom   = (const int*)d_in[3];    // [128,128,128,6] i32
    float* out = (float*)d_out;

    // Phase 1: pack (TABLE_N divisible by 4)
    {
        int nvec = TABLE_N / 4;
        pack_kernel<<<(nvec + 255) / 256, 256>>>(
            (const int4*)numer, (const int4*)denom, nvec);
    }

    // Phase 2: TMA-staged gather, 1024 rays/block
    int nrays  = in_sizes[0] / 3;
    int nfull  = nrays / RAYS_PER_BLOCK;
    if (nfull > 0) {
        vis_cache_kernel<<<nfull, 256>>>(origins, dirs, (float4*)out);
    }
    int tail_start = nfull * RAYS_PER_BLOCK;
    int tail = nrays - tail_start;
    if (tail > 0) {
        vis_cache_tail<<<(tail + 255) / 256, 256>>>(
            origins, dirs, out, tail_start, nrays);
    }
}

// round 14
// speedup vs baseline: 1.3567x; 1.3567x over previous
#include <cuda_runtime.h>
#include <cuda_bf16.h>

// NaiveVisCache R13: best-measured configuration (R9 gather + R9/R11 pack).
//  Phase 1: pack (n | d<<8) u16 -> 25MB table, evict_last, 4 entries/thread.
//           At DRAM floor (~16us for 125MB).
//  Phase 2: 4 rays/thread, launch_bounds(256,8), __ldcs streams, batched
//           evict_last gathers (NO .nc: R9's 33.86us vs R11's 34.94 with .nc).
//           At the L1tex wavefront floor: 4.19M divergent gathers x 2.07
//           cyc/wf / 148 SM ~= 33.5us. R12's TMA staging regressed (58us,
//           exposed serial TMA latency) -> reverted.
// Numerics bit-exact (rel_err 0.0 since R4): face via rcp.rn+mul (matches
// XLA's div-by-broadcast-scalar rewrite), output via fdiv_rn on the exact
// small-int n,d recovered from the packed u16.

#define VGRID 128
#define TABLE_N (VGRID * VGRID * VGRID * 6)   // 12,582,912 entries

__device__ unsigned short g_pack[TABLE_N];    // 25.2MB static scratch

__device__ __forceinline__ unsigned long long evict_last_policy() {
    unsigned long long pol;
    asm("createpolicy.fractional.L2::evict_last.b64 %0, 1.0;" : "=l"(pol));
    return pol;
}

// ---------------- Phase 1: pack tables (4 entries/thread) ----------------
__global__ void __launch_bounds__(256)
pack_kernel(const int4* __restrict__ numer4,
            const int4* __restrict__ denom4,
            int nvec) {
    int t = blockIdx.x * blockDim.x + threadIdx.x;
    if (t >= nvec) return;
    unsigned long long pol = evict_last_policy();

    int4 n = __ldcs(numer4 + t);   // touch-once streams
    int4 d = __ldcs(denom4 + t);
    unsigned int lo = (unsigned int)(n.x | (d.x << 8)) |
                      ((unsigned int)(n.y | (d.y << 8)) << 16);
    unsigned int hi = (unsigned int)(n.z | (d.z << 8)) |
                      ((unsigned int)(n.w | (d.w << 8)) << 16);
    unsigned long long v = (unsigned long long)lo | ((unsigned long long)hi << 32);
    asm volatile("st.global.L2::cache_hint.b64 [%0], %1, %2;"
                 :: "l"((unsigned long long*)(g_pack + 4 * (size_t)t)),
                    "l"(v), "l"(pol));
}

// ---------------- index math (bit-exact vs reference) ----------------
__device__ __forceinline__ int coord_clip(float o) {
    float t = (o * 0.5f + 0.5f) * (float)(VGRID - 1);
    t = fminf(fmaxf(t, 0.0f), (float)(VGRID - 1));
    return (int)t;
}

__device__ __forceinline__ int ray_index(float o0, float o1, float o2,
                                         float d0, float d1, float d2) {
    float inf = fmaxf(fabsf(d0), fmaxf(fabsf(d1), fabsf(d2)));
    // Reference: sqdirs = viewdirs * RN(1/inf_norm) (verified bit-exact, R4).
    float rinf = __frcp_rn(inf);
    float sa = d0 * rinf;
    float sb = d1 * rinf;
    float sc = d2 * rinf;
    int f = 0;
    if (sa >=  1.0f) f = 0;
    if (sa <= -1.0f) f = 1;
    if (sb >=  1.0f) f = 2;
    if (sb <= -1.0f) f = 3;
    if (sc >=  1.0f) f = 4;
    if (sc <= -1.0f) f = 5;
    int i = coord_clip(o0);
    int j = coord_clip(o1);
    int k = coord_clip(o2);
    return (((i * VGRID + j) * VGRID + k) * 6) + f;
}

__device__ __forceinline__ unsigned int gather_pack(int idx,
                                                    unsigned long long pol) {
    unsigned int v;
    asm volatile("ld.global.L2::cache_hint.u16 %0, [%1], %2;"
                 : "=r"(v) : "l"(g_pack + idx), "l"(pol));
    return v;
}

__device__ __forceinline__ float decode_div(unsigned int p) {
    float n = (float)(int)(p & 0xFFu);
    float d = (float)(int)(p >> 8);
    return __fdiv_rn(n, d);   // same instruction/values as reference path
}

// ---------------- Phase 2: gather, 4 rays/thread ----------------
__global__ void __launch_bounds__(256, 8)
vis_cache_kernel(const float4* __restrict__ o4,
                 const float4* __restrict__ v4,
                 float4*       __restrict__ out,
                 int nquads) {
    int t = blockIdx.x * blockDim.x + threadIdx.x;
    if (t >= nquads) return;
    unsigned long long pol = evict_last_policy();

    float4 oa = __ldcs(o4 + 3 * t + 0);
    float4 ob = __ldcs(o4 + 3 * t + 1);
    float4 oc = __ldcs(o4 + 3 * t + 2);
    float4 va = __ldcs(v4 + 3 * t + 0);
    float4 vb = __ldcs(v4 + 3 * t + 1);
    float4 vc = __ldcs(v4 + 3 * t + 2);

    int idx0 = ray_index(oa.x, oa.y, oa.z, va.x, va.y, va.z);
    int idx1 = ray_index(oa.w, ob.x, ob.y, va.w, vb.x, vb.y);
    int idx2 = ray_index(ob.z, ob.w, oc.x, vb.z, vb.w, vc.x);
    int idx3 = ray_index(oc.y, oc.z, oc.w, vc.y, vc.z, vc.w);

    // Batched divergent gathers (MLP=4) from the L2-resident 25MB table.
    unsigned int p0 = gather_pack(idx0, pol);
    unsigned int p1 = gather_pack(idx1, pol);
    unsigned int p2 = gather_pack(idx2, pol);
    unsigned int p3 = gather_pack(idx3, pol);

    float4 r;
    r.x = decode_div(p0);
    r.y = decode_div(p1);
    r.z = decode_div(p2);
    r.w = decode_div(p3);
    __stcs(out + t, r);
}

__global__ void __launch_bounds__(256)
vis_cache_tail(const float* __restrict__ origins,
               const float* __restrict__ dirs,
               float*       __restrict__ out,
               int start, int nrays) {
    int r = start + blockIdx.x * blockDim.x + threadIdx.x;
    if (r >= nrays) return;
    int idx = ray_index(origins[3 * r], origins[3 * r + 1], origins[3 * r + 2],
                        dirs[3 * r],    dirs[3 * r + 1],    dirs[3 * r + 2]);
    unsigned int p = g_pack[idx];
    out[r] = __fdiv_rn((float)(int)(p & 0xFFu), (float)(int)(p >> 8));
}

extern "C" void kernel_launch(void* const* d_in, const int* in_sizes, int n_in,
                              void* d_out, int out_size) {
    const float* origins = (const float*)d_in[0];  // [B,3] f32
    const float* dirs    = (const float*)d_in[1];  // [B,3] f32
    const int*   numer   = (const int*)d_in[2];    // [128,128,128,6] i32
    const int*   denom   = (const int*)d_in[3];    // [128,128,128,6] i32
    float* out = (float*)d_out;

    // Phase 1: pack (TABLE_N divisible by 4)
    {
        int nvec = TABLE_N / 4;
        pack_kernel<<<(nvec + 255) / 256, 256>>>(
            (const int4*)numer, (const int4*)denom, nvec);
    }

    // Phase 2: gather, 4 rays/thread
    int nrays  = in_sizes[0] / 3;
    int nquads = nrays >> 2;
    if (nquads > 0) {
        vis_cache_kernel<<<(nquads + 255) / 256, 256>>>(
            (const float4*)origins, (const float4*)dirs, (float4*)out, nquads);
    }
    int tail_start = nquads << 2;
    int tail = nrays - tail_start;
    if (tail > 0) {
        vis_cache_tail<<<(tail + 255) / 256, 256>>>(
            origins, dirs, out, tail_start, nrays);
    }
}